// round 8
// baseline (speedup 1.0000x reference)
#include <cuda_runtime.h>
#include <cstdint>

// Problem constants (fixed by the reference: B=2, G=64)
constexpr int G3      = 64 * 64 * 64;   // 262144 voxels per batch
constexpr int NB      = 2;
constexpr int THREADS = 256;

// Packed f32x2 ops (PTX-only; ptxas never auto-fuses FFMA2 from C++).
__device__ __forceinline__ uint64_t fma2(uint64_t a, uint64_t b, uint64_t c) {
    uint64_t d;
    asm("fma.rn.f32x2 %0, %1, %2, %3;" : "=l"(d) : "l"(a), "l"(b), "l"(c));
    return d;
}
__device__ __forceinline__ uint64_t mul2(uint64_t a, uint64_t b) {
    uint64_t d;
    asm("mul.rn.f32x2 %0, %1, %2;" : "=l"(d) : "l"(a), "l"(b));
    return d;
}

// C_ijkl[b,v] = sum_{mnop} a[b,m,i,v] a[b,n,j,v] a[b,o,k,v] a[b,p,l,v] C0[mnop]
// One thread = one voxel pair (packed f32x2 lanes), rolled i-loop (one-i live
// set), C0 in shared. The __launch_bounds__(256,2) register budget (128) is
// what keeps the 81 C0 words in smem instead of hoisted into ~162 registers
// (R6: 255 regs, 1 CTA/SM). Plain (non-volatile) shared loads let ptxas
// software-pipeline the stage-1 LDS against FFMA2 chains and the previous
// iteration's stores — R7's asm-volatile loads pinned program order and left
// issue at 30%.
__global__ __launch_bounds__(THREADS, 2)
void alphaC0_42C_kernel(const float* __restrict__ a,
                        const float* __restrict__ c0,
                        float* __restrict__ out)
{
    // sc0 splatted to both f32x2 lanes so it is directly an FFMA2 operand.
    __shared__ uint64_t sc0[81];
    if (threadIdx.x < 81) {
        float c = c0[threadIdx.x];
        float2 cc = make_float2(c, c);
        sc0[threadIdx.x] = *reinterpret_cast<uint64_t*>(&cc);
    }
    __syncthreads();

    // Global pair index over the flattened (b, voxel) axis. G3 even -> no
    // pair crosses the batch boundary; NB==2 -> batch select by compare.
    const long pair = (long)blockIdx.x * THREADS + threadIdx.x;
    const long v2   = pair * 2;
    const int  b    = (v2 >= G3) ? 1 : 0;
    const long v    = v2 - (long)b * G3;

    // Load the 3x3 per-voxel matrix a[m][i] for both voxels of the pair.
    const float* ap = a + (long)b * 9 * G3 + v;
    uint64_t A[9];
#pragma unroll
    for (int mi = 0; mi < 9; ++mi)
        A[mi] = *reinterpret_cast<const uint64_t*>(ap + (long)mi * G3);

    float* ob = out + (long)b * 81 * G3 + v;

#pragma unroll 1   // rolled: one-i live set; full unroll spilled (R3)
    for (int i = 0; i < 3; ++i) {
        // Stage 1: T1[n,o,p] = sum_m A[m,i] * C0[m,n,o,p]  (C0 from smem)
        uint64_t T1[27];
#pragma unroll
        for (int nop = 0; nop < 27; ++nop) {
            uint64_t s = mul2(A[0 * 3 + i], sc0[nop]);
            s = fma2(A[1 * 3 + i], sc0[27 + nop], s);
            s = fma2(A[2 * 3 + i], sc0[54 + nop], s);
            T1[nop] = s;
        }
        // Per-i output base: in-iteration store offsets are compile-time
        // constants -> STG [reg+imm], minimal address arithmetic.
        float* obi = ob + (long)i * 27 * G3;
#pragma unroll
        for (int j = 0; j < 3; ++j) {
            // Stage 2: T2[o,p] = sum_n A[n,j] * T1[n,o,p]
            uint64_t T2[9];
#pragma unroll
            for (int op = 0; op < 9; ++op) {
                uint64_t s = mul2(A[0 * 3 + j], T1[op]);
                s = fma2(A[1 * 3 + j], T1[9 + op], s);
                s = fma2(A[2 * 3 + j], T1[18 + op], s);
                T2[op] = s;
            }
#pragma unroll
            for (int k = 0; k < 3; ++k) {
                // Stage 3: T3[p] = sum_o A[o,k] * T2[o,p]
                uint64_t T3[3];
#pragma unroll
                for (int p = 0; p < 3; ++p) {
                    uint64_t s = mul2(A[0 * 3 + k], T2[p]);
                    s = fma2(A[1 * 3 + k], T2[3 + p], s);
                    s = fma2(A[2 * 3 + k], T2[6 + p], s);
                    T3[p] = s;
                }
#pragma unroll
                for (int l = 0; l < 3; ++l) {
                    // Stage 4: C[i,j,k,l] = sum_p A[p,l] * T3[p]
                    uint64_t r = mul2(A[0 * 3 + l], T3[0]);
                    r = fma2(A[1 * 3 + l], T3[1], r);
                    r = fma2(A[2 * 3 + l], T3[2], r);
                    // Coalesced STG.64, default L2 write-back (streaming
                    // hints hurt — R2 evidence).
                    *reinterpret_cast<uint64_t*>(
                        obi + ((j * 3 + k) * 3 + l) * G3) = r;
                }
            }
        }
    }
}

extern "C" void kernel_launch(void* const* d_in, const int* in_sizes, int n_in,
                              void* d_out, int out_size)
{
    const float* a   = (const float*)d_in[0];   // alphatensor (2,3,3,64,64,64)
    const float* c0  = (const float*)d_in[1];   // C0_4 (3,3,3,3)
    float*       out = (float*)d_out;           // (2,3,3,3,3,64,64,64)

    const long total_pairs = (long)NB * G3 / 2;            // 262144
    const int  blocks      = (int)(total_pairs / THREADS); // 1024
    alphaC0_42C_kernel<<<blocks, THREADS>>>(a, c0, out);
}

// round 9
// speedup vs baseline: 1.2379x; 1.2379x over previous
#include <cuda_runtime.h>
#include <cstdint>

// Problem constants (fixed by the reference: B=2, G=64)
constexpr int G3      = 64 * 64 * 64;   // 262144 voxels per batch
constexpr int NB      = 2;
constexpr int THREADS = 256;

// C0 lives in constant memory: LDC uses the constant port, NOT the LSU.
// R7 analysis showed the kernel is LSU-throughput bound (81 STG.64 + 243 LDS
// per warp ~= the whole kernel duration); moving the 243 C0 reads off the LSU
// is the direct fix. Filled by cudaMemcpyToSymbolAsync (D2D, capturable).
__constant__ float dc0[81];

// Packed f32x2 ops (PTX-only; ptxas never auto-fuses FFMA2 from C++).
__device__ __forceinline__ uint64_t fma2(uint64_t a, uint64_t b, uint64_t c) {
    uint64_t d;
    asm("fma.rn.f32x2 %0, %1, %2, %3;" : "=l"(d) : "l"(a), "l"(b), "l"(c));
    return d;
}
__device__ __forceinline__ uint64_t mul2(uint64_t a, uint64_t b) {
    uint64_t d;
    asm("mul.rn.f32x2 %0, %1, %2;" : "=l"(d) : "l"(a), "l"(b));
    return d;
}
// Un-hoistable constant load + splat to both f32x2 lanes.
// volatile is load-bearing: without it ptxas hoists all 81 C0 words into
// registers, blows past the 128-reg budget and spills (R6: 255 regs; R8:
// spill traffic). MOV.b64 pack rides the idle alu pipe.
__device__ __forceinline__ uint64_t ldc_splat(uint64_t caddr) {
    uint32_t v;
    uint64_t d;
    asm volatile("ld.const.b32 %0, [%1];" : "=r"(v) : "l"(caddr));
    asm("mov.b64 %0, {%1, %1};" : "=l"(d) : "r"(v));
    return d;
}

// C_ijkl[b,v] = sum_{mnop} a[b,m,i,v] a[b,n,j,v] a[b,o,k,v] a[b,p,l,v] C0[mnop]
// One thread = one voxel pair (packed f32x2 lanes), rolled i-loop (one-i live
// set ~120 regs), 2 CTAs/SM.
__global__ __launch_bounds__(THREADS, 2)
void alphaC0_42C_kernel(const float* __restrict__ a,
                        float* __restrict__ out)
{
    // Const-space base address of dc0 (cvta once).
    uint64_t cbase;
    asm("cvta.to.const.u64 %0, %1;" : "=l"(cbase) : "l"((const void*)dc0));

    // Global pair index over the flattened (b, voxel) axis. G3 even -> no
    // pair crosses the batch boundary; NB==2 -> batch select by compare.
    const long pair = (long)blockIdx.x * THREADS + threadIdx.x;
    const long v2   = pair * 2;
    const int  b    = (v2 >= G3) ? 1 : 0;
    const long v    = v2 - (long)b * G3;

    // Load the 3x3 per-voxel matrix a[m][i] for both voxels of the pair.
    const float* ap = a + (long)b * 9 * G3 + v;
    uint64_t A[9];
#pragma unroll
    for (int mi = 0; mi < 9; ++mi)
        A[mi] = *reinterpret_cast<const uint64_t*>(ap + (long)mi * G3);

    float* ob = out + (long)b * 81 * G3 + v;

#pragma unroll 1   // rolled: one-i live set; full unroll spilled (R3)
    for (int i = 0; i < 3; ++i) {
        // Stage 1: T1[n,o,p] = sum_m A[m,i] * C0[m,n,o,p]  (C0 via LDC)
        uint64_t T1[27];
#pragma unroll
        for (int nop = 0; nop < 27; ++nop) {
            uint64_t s = mul2(A[0 * 3 + i], ldc_splat(cbase + nop * 4u));
            s = fma2(A[1 * 3 + i], ldc_splat(cbase + (27 + nop) * 4u), s);
            s = fma2(A[2 * 3 + i], ldc_splat(cbase + (54 + nop) * 4u), s);
            T1[nop] = s;
        }
#pragma unroll
        for (int j = 0; j < 3; ++j) {
            // Stage 2: T2[o,p] = sum_n A[n,j] * T1[n,o,p]
            uint64_t T2[9];
#pragma unroll
            for (int op = 0; op < 9; ++op) {
                uint64_t s = mul2(A[0 * 3 + j], T1[op]);
                s = fma2(A[1 * 3 + j], T1[9 + op], s);
                s = fma2(A[2 * 3 + j], T1[18 + op], s);
                T2[op] = s;
            }
#pragma unroll
            for (int k = 0; k < 3; ++k) {
                // Stage 3: T3[p] = sum_o A[o,k] * T2[o,p]
                uint64_t T3[3];
#pragma unroll
                for (int p = 0; p < 3; ++p) {
                    uint64_t s = mul2(A[0 * 3 + k], T2[p]);
                    s = fma2(A[1 * 3 + k], T2[3 + p], s);
                    s = fma2(A[2 * 3 + k], T2[6 + p], s);
                    T3[p] = s;
                }
#pragma unroll
                for (int l = 0; l < 3; ++l) {
                    // Stage 4: C[i,j,k,l] = sum_p A[p,l] * T3[p]
                    uint64_t r = mul2(A[0 * 3 + l], T3[0]);
                    r = fma2(A[1 * 3 + l], T3[1], r);
                    r = fma2(A[2 * 3 + l], T3[2], r);
                    // Coalesced STG.64, default L2 write-back (streaming
                    // hints hurt — R2 evidence).
                    *reinterpret_cast<uint64_t*>(
                        ob + (long)(((i * 3 + j) * 3 + k) * 3 + l) * G3) = r;
                }
            }
        }
    }
}

extern "C" void kernel_launch(void* const* d_in, const int* in_sizes, int n_in,
                              void* d_out, int out_size)
{
    const float* a   = (const float*)d_in[0];   // alphatensor (2,3,3,64,64,64)
    const float* c0  = (const float*)d_in[1];   // C0_4 (3,3,3,3)
    float*       out = (float*)d_out;           // (2,3,3,3,3,64,64,64)

    // Stage C0 into constant memory (D2D async copy: graph-capturable,
    // no allocation).
    cudaMemcpyToSymbolAsync(dc0, c0, 81 * sizeof(float), 0,
                            cudaMemcpyDeviceToDevice);

    const long total_pairs = (long)NB * G3 / 2;            // 262144
    const int  blocks      = (int)(total_pairs / THREADS); // 1024
    alphaC0_42C_kernel<<<blocks, THREADS>>>(a, out);
}

// round 10
// speedup vs baseline: 1.2888x; 1.0411x over previous
#include <cuda_runtime.h>
#include <cstdint>

// Problem constants (fixed by the reference: B=2, G=64)
constexpr int G3      = 64 * 64 * 64;   // 262144 voxels per batch
constexpr int NB      = 2;
constexpr int THREADS = 256;

// Packed f32x2 ops (PTX-only; ptxas never auto-fuses FFMA2 from C++).
__device__ __forceinline__ uint64_t fma2(uint64_t a, uint64_t b, uint64_t c) {
    uint64_t d;
    asm("fma.rn.f32x2 %0, %1, %2, %3;" : "=l"(d) : "l"(a), "l"(b), "l"(c));
    return d;
}
__device__ __forceinline__ uint64_t mul2(uint64_t a, uint64_t b) {
    uint64_t d;
    asm("mul.rn.f32x2 %0, %1, %2;" : "=l"(d) : "l"(a), "l"(b));
    return d;
}
// Un-hoistable shared loads (volatile is load-bearing: plain loads let ptxas
// hoist all 81 C0 words into ~162 regs -> spills; R6/R8 evidence).
__device__ __forceinline__ uint64_t lds64(uint32_t saddr) {
    uint64_t d;
    asm volatile("ld.shared.b64 %0, [%1];" : "=l"(d) : "r"(saddr));
    return d;
}
__device__ __forceinline__ void lds128(uint32_t saddr, uint64_t& d0, uint64_t& d1) {
    asm volatile("ld.shared.v2.b64 {%0, %1}, [%2];"
                 : "=l"(d0), "=l"(d1) : "r"(saddr));
}
__device__ __forceinline__ uint32_t smem_u32(const void* p) {
    uint32_t r;
    asm("{ .reg .u64 t; cvta.to.shared.u64 t, %1; cvt.u32.u64 %0, t; }"
        : "=r"(r) : "l"(p));
    return r;
}

// C_ijkl[b,v] = sum_{mnop} a[b,m,i,v] a[b,n,j,v] a[b,o,k,v] a[b,p,l,v] C0[mnop]
// One thread = one voxel pair (packed f32x2 lanes), rolled i-loop (one-i live
// set, ~124 regs), C0 in shared with m-FASTEST layout so stage 1 reads 6
// consecutive u64 per 2 nop -> 3x LDS.128 instead of 6x LDS.64 (243 -> 123
// shared loads per thread). 2 CTAs/SM.
__global__ __launch_bounds__(THREADS, 2)
void alphaC0_42C_kernel(const float* __restrict__ a,
                        const float* __restrict__ c0,
                        float* __restrict__ out)
{
    // sc0m[nop*3 + m] = splat(c0[m*27 + nop]) — m fastest, both f32x2 lanes.
    __shared__ __align__(16) uint64_t sc0m[82];  // 82: keep v2 reads in-bounds
    if (threadIdx.x < 81) {
        int m   = threadIdx.x / 27;
        int nop = threadIdx.x % 27;
        float c = c0[threadIdx.x];
        float2 cc = make_float2(c, c);
        sc0m[nop * 3 + m] = *reinterpret_cast<uint64_t*>(&cc);
    }
    __syncthreads();
    const uint32_t sbase = smem_u32(sc0m);

    // Global pair index over the flattened (b, voxel) axis. G3 even -> no
    // pair crosses the batch boundary; NB==2 -> batch select by compare.
    const long pair = (long)blockIdx.x * THREADS + threadIdx.x;
    const long v2   = pair * 2;
    const int  b    = (v2 >= G3) ? 1 : 0;
    const long v    = v2 - (long)b * G3;

    // Load the 3x3 per-voxel matrix a[m][i] for both voxels of the pair.
    const float* ap = a + (long)b * 9 * G3 + v;
    uint64_t A[9];
#pragma unroll
    for (int mi = 0; mi < 9; ++mi)
        A[mi] = *reinterpret_cast<const uint64_t*>(ap + (long)mi * G3);

    float* ob = out + (long)b * 81 * G3 + v;

#pragma unroll 1   // rolled: one-i live set; full unroll spilled (R3)
    for (int i = 0; i < 3; ++i) {
        const uint64_t Ai0 = A[0 * 3 + i], Ai1 = A[1 * 3 + i], Ai2 = A[2 * 3 + i];
        // Stage 1: T1[n,o,p] = sum_m A[m,i] * C0[m,n,o,p]
        // Two nop per step: 6 consecutive u64 -> 3 LDS.128 (16B-aligned,
        // uniform address => conflict-free broadcast).
        uint64_t T1[27];
#pragma unroll
        for (int t = 0; t < 13; ++t) {
            uint64_t c0a, c0b, c0c, c0d, c0e, c0f;
            const uint32_t addr = sbase + (uint32_t)(t * 48);  // 6 u64 / step
            lds128(addr,      c0a, c0b);   // nop=2t:   m=0,1
            lds128(addr + 16, c0c, c0d);   // nop=2t m=2; nop=2t+1 m=0
            lds128(addr + 32, c0e, c0f);   // nop=2t+1: m=1,2
            T1[2 * t]     = fma2(Ai2, c0c, fma2(Ai1, c0b, mul2(Ai0, c0a)));
            T1[2 * t + 1] = fma2(Ai2, c0f, fma2(Ai1, c0e, mul2(Ai0, c0d)));
        }
        {   // nop = 26
            uint64_t c0a, c0b, c0c;
            const uint32_t addr = sbase + 26u * 24u;
            lds128(addr, c0a, c0b);
            c0c = lds64(addr + 16);
            T1[26] = fma2(Ai2, c0c, fma2(Ai1, c0b, mul2(Ai0, c0a)));
        }
        // Per-i output base: in-iteration offsets are compile-time constants.
        float* obi = ob + (long)i * 27 * G3;
#pragma unroll
        for (int j = 0; j < 3; ++j) {
            // Stage 2: T2[o,p] = sum_n A[n,j] * T1[n,o,p]
            uint64_t T2[9];
#pragma unroll
            for (int op = 0; op < 9; ++op) {
                uint64_t s = mul2(A[0 * 3 + j], T1[op]);
                s = fma2(A[1 * 3 + j], T1[9 + op], s);
                s = fma2(A[2 * 3 + j], T1[18 + op], s);
                T2[op] = s;
            }
#pragma unroll
            for (int k = 0; k < 3; ++k) {
                // Stage 3: T3[p] = sum_o A[o,k] * T2[o,p]
                uint64_t T3[3];
#pragma unroll
                for (int p = 0; p < 3; ++p) {
                    uint64_t s = mul2(A[0 * 3 + k], T2[p]);
                    s = fma2(A[1 * 3 + k], T2[3 + p], s);
                    s = fma2(A[2 * 3 + k], T2[6 + p], s);
                    T3[p] = s;
                }
#pragma unroll
                for (int l = 0; l < 3; ++l) {
                    // Stage 4: C[i,j,k,l] = sum_p A[p,l] * T3[p]
                    uint64_t r = mul2(A[0 * 3 + l], T3[0]);
                    r = fma2(A[1 * 3 + l], T3[1], r);
                    r = fma2(A[2 * 3 + l], T3[2], r);
                    // Coalesced STG.64, default L2 write-back (streaming
                    // hints hurt — R2 evidence).
                    *reinterpret_cast<uint64_t*>(
                        obi + ((j * 3 + k) * 3 + l) * G3) = r;
                }
            }
        }
    }
}

extern "C" void kernel_launch(void* const* d_in, const int* in_sizes, int n_in,
                              void* d_out, int out_size)
{
    const float* a   = (const float*)d_in[0];   // alphatensor (2,3,3,64,64,64)
    const float* c0  = (const float*)d_in[1];   // C0_4 (3,3,3,3)
    float*       out = (float*)d_out;           // (2,3,3,3,3,64,64,64)

    const long total_pairs = (long)NB * G3 / 2;            // 262144
    const int  blocks      = (int)(total_pairs / THREADS); // 1024
    alphaC0_42C_kernel<<<blocks, THREADS>>>(a, c0, out);
}

// round 11
// speedup vs baseline: 1.3142x; 1.0197x over previous
#include <cuda_runtime.h>
#include <cstdint>

// Problem constants (fixed by the reference: B=2, G=64)
constexpr int G3      = 64 * 64 * 64;   // 262144 voxels per batch
constexpr int NB      = 2;
constexpr int THREADS = 256;

// Packed f32x2 ops (PTX-only; ptxas never auto-fuses FFMA2 from C++).
__device__ __forceinline__ uint64_t fma2(uint64_t a, uint64_t b, uint64_t c) {
    uint64_t d;
    asm("fma.rn.f32x2 %0, %1, %2, %3;" : "=l"(d) : "l"(a), "l"(b), "l"(c));
    return d;
}
__device__ __forceinline__ uint64_t mul2(uint64_t a, uint64_t b) {
    uint64_t d;
    asm("mul.rn.f32x2 %0, %1, %2;" : "=l"(d) : "l"(a), "l"(b));
    return d;
}
// Un-hoistable shared load (volatile is load-bearing: plain loads let ptxas
// hoist all 81 C0 words into ~162 regs -> spills; R6/R8 evidence).
__device__ __forceinline__ uint64_t lds64(uint32_t saddr) {
    uint64_t d;
    asm volatile("ld.shared.b64 %0, [%1];" : "=l"(d) : "r"(saddr));
    return d;
}
__device__ __forceinline__ uint32_t smem_u32(const void* p) {
    uint32_t r;
    asm("{ .reg .u64 t; cvta.to.shared.u64 t, %1; cvt.u32.u64 %0, t; }"
        : "=r"(r) : "l"(p));
    return r;
}

// C_ijkl[b,v] = sum_{mnop} a[b,m,i,v] a[b,n,j,v] a[b,o,k,v] a[b,p,l,v] C0[mnop]
// R7 structure (best so far: voxel-pair threads, rolled i, C0 in smem via
// volatile LDS.64, 2 CTAs/SM) + a one-step C0 PREFETCH rotation in stage 1:
// while computing nop's chain, nop+1's three C0 words are already in flight,
// hiding the 29-cycle LDS latency that R7/R10 exposed on every step.
// 32-bit offset addressing funds the +6 prefetch registers under the 128 cap.
__global__ __launch_bounds__(THREADS, 2)
void alphaC0_42C_kernel(const float* __restrict__ a,
                        const float* __restrict__ c0,
                        float* __restrict__ out)
{
    // sc0[m*27+nop] splatted to both f32x2 lanes (direct FFMA2 operand).
    __shared__ uint64_t sc0[81];
    if (threadIdx.x < 81) {
        float c = c0[threadIdx.x];
        float2 cc = make_float2(c, c);
        sc0[threadIdx.x] = *reinterpret_cast<uint64_t*>(&cc);
    }
    __syncthreads();
    const uint32_t sbase = smem_u32(sc0);

    // Flattened (b, voxel-pair) index; G3 even -> pairs never straddle b.
    const long pair = (long)blockIdx.x * THREADS + threadIdx.x;
    const long v2   = pair * 2;
    const int  b    = (v2 >= G3) ? 1 : 0;
    const uint32_t v = (uint32_t)(v2 - (long)b * G3);

    // Load the 3x3 per-voxel matrix a[m][i] for both voxels of the pair.
    // 32-bit element offsets (max 85 MB of floats -> fits u32 easily).
    const float* ab = a + (long)b * 9 * G3;
    uint64_t A[9];
#pragma unroll
    for (int mi = 0; mi < 9; ++mi)
        A[mi] = *reinterpret_cast<const uint64_t*>(ab + (uint32_t)(mi * G3) + v);

    float* ob = out + (long)b * 81 * G3 + v;

#pragma unroll 1   // rolled: one-i live set (~125 regs); full unroll spilled (R3)
    for (int i = 0; i < 3; ++i) {
        const uint64_t Ai0 = A[0 * 3 + i], Ai1 = A[1 * 3 + i], Ai2 = A[2 * 3 + i];

        // Stage 1 with one-step software prefetch of the three C0 operands.
        uint64_t T1[27];
        uint64_t n0 = lds64(sbase);            // nop=0: m=0
        uint64_t n1 = lds64(sbase + 27 * 8u);  //        m=1
        uint64_t n2 = lds64(sbase + 54 * 8u);  //        m=2
#pragma unroll
        for (int nop = 0; nop < 27; ++nop) {
            const uint64_t c0a = n0, c0b = n1, c0c = n2;
            if (nop < 26) {   // issue next step's loads BEFORE consuming this one
                n0 = lds64(sbase + (uint32_t)((nop + 1) * 8));
                n1 = lds64(sbase + (uint32_t)((28 + nop) * 8));
                n2 = lds64(sbase + (uint32_t)((55 + nop) * 8));
            }
            uint64_t s = mul2(Ai0, c0a);
            s = fma2(Ai1, c0b, s);
            s = fma2(Ai2, c0c, s);
            T1[nop] = s;
        }

        // Per-i output base: in-iteration offsets are compile-time constants.
        float* obi = ob + (uint32_t)(i * 27 * G3);
#pragma unroll
        for (int j = 0; j < 3; ++j) {
            // Stage 2: T2[o,p] = sum_n A[n,j] * T1[n,o,p]
            uint64_t T2[9];
#pragma unroll
            for (int op = 0; op < 9; ++op) {
                uint64_t s = mul2(A[0 * 3 + j], T1[op]);
                s = fma2(A[1 * 3 + j], T1[9 + op], s);
                s = fma2(A[2 * 3 + j], T1[18 + op], s);
                T2[op] = s;
            }
#pragma unroll
            for (int k = 0; k < 3; ++k) {
                // Stage 3: T3[p] = sum_o A[o,k] * T2[o,p]
                uint64_t T3[3];
#pragma unroll
                for (int p = 0; p < 3; ++p) {
                    uint64_t s = mul2(A[0 * 3 + k], T2[p]);
                    s = fma2(A[1 * 3 + k], T2[3 + p], s);
                    s = fma2(A[2 * 3 + k], T2[6 + p], s);
                    T3[p] = s;
                }
#pragma unroll
                for (int l = 0; l < 3; ++l) {
                    // Stage 4: C[i,j,k,l] = sum_p A[p,l] * T3[p]
                    uint64_t r = mul2(A[0 * 3 + l], T3[0]);
                    r = fma2(A[1 * 3 + l], T3[1], r);
                    r = fma2(A[2 * 3 + l], T3[2], r);
                    // Coalesced STG.64, default L2 write-back (streaming
                    // hints hurt — R2 evidence).
                    *reinterpret_cast<uint64_t*>(
                        obi + (uint32_t)(((j * 3 + k) * 3 + l) * G3)) = r;
                }
            }
        }
    }
}

extern "C" void kernel_launch(void* const* d_in, const int* in_sizes, int n_in,
                              void* d_out, int out_size)
{
    const float* a   = (const float*)d_in[0];   // alphatensor (2,3,3,64,64,64)
    const float* c0  = (const float*)d_in[1];   // C0_4 (3,3,3,3)
    float*       out = (float*)d_out;           // (2,3,3,3,3,64,64,64)

    const long total_pairs = (long)NB * G3 / 2;            // 262144
    const int  blocks      = (int)(total_pairs / THREADS); // 1024
    alphaC0_42C_kernel<<<blocks, THREADS>>>(a, c0, out);
}